// round 1
// baseline (speedup 1.0000x reference)
#include <cuda_runtime.h>
#include <cuda_bf16.h>

// Problem constants
#define HH 64
#define WW 64
#define CIN 256
#define COUT 256
#define BB 8
#define KKT 9
#define HWSZ 4096            // H*W
#define KTOT 2304            // 9*256

// ---------------- scratch (device globals: no allocation allowed) ----------
__device__ float  g_xn[BB * HWSZ * CIN];     // x in NHWC           (33.5 MB)
__device__ float  g_wT[KTOT * COUT];         // W^T [k][oc], k=tap*256+c
__device__ float  g_wom[KKT * 27 * CIN];     // fused off/mod weights [tap][oc][c]
__device__ short4 g_sxy[BB * KKT * HWSZ];    // clamped corner coords (y0,y1,x0,x1)
__device__ float4 g_swt[BB * KKT * HWSZ];    // bilinear*mask*valid weights

// ---------------- f32x2 helpers --------------------------------------------
__device__ __forceinline__ unsigned long long fma2(unsigned long long a,
                                                   unsigned long long b,
                                                   unsigned long long c) {
    unsigned long long d;
    asm("fma.rn.f32x2 %0, %1, %2, %3;" : "=l"(d) : "l"(a), "l"(b), "l"(c));
    return d;
}
__device__ __forceinline__ float2 upk2(unsigned long long v) {
    float2 r;
    asm("mov.b64 {%0, %1}, %2;" : "=f"(r.x), "=f"(r.y) : "l"(v));
    return r;
}

// ---------------- kernel: NCHW -> NHWC transpose of x ----------------------
__global__ void k_transpose(const float* __restrict__ x) {
    __shared__ float tile[32][33];
    int b  = blockIdx.z;
    int p0 = blockIdx.x * 32;   // spatial
    int c0 = blockIdx.y * 32;   // channel
    const float* xb = x   + (size_t)b * (CIN * HWSZ);
    float*       ob = g_xn + (size_t)b * (HWSZ * CIN);
    int tx = threadIdx.x, ty = threadIdx.y;
#pragma unroll
    for (int i = 0; i < 4; i++)
        tile[ty + i * 8][tx] = xb[(size_t)(c0 + ty + i * 8) * HWSZ + p0 + tx];
    __syncthreads();
#pragma unroll
    for (int i = 0; i < 4; i++)
        ob[(size_t)(p0 + ty + i * 8) * CIN + c0 + tx] = tile[tx][ty + i * 8];
}

// ---------------- kernel: transpose reg_w to [k][oc] -----------------------
__global__ void k_wt(const float* __restrict__ reg_w) {
    int idx = blockIdx.x * 256 + threadIdx.x;   // = k*256 + oc
    if (idx >= KTOT * COUT) return;
    int oc  = idx & 255;
    int k   = idx >> 8;
    int tap = k >> 8;
    int c   = k & 255;
    g_wT[idx] = reg_w[(size_t)(oc * CIN + c) * KKT + tap];
}

// ---------------- kernel: fuse offset_w + mod_w into [tap][oc][c] ----------
__global__ void k_wom(const float* __restrict__ ow, const float* __restrict__ mw) {
    int idx = blockIdx.x * 256 + threadIdx.x;
    if (idx >= KKT * 27 * CIN) return;
    int c   = idx & 255;
    int r   = idx >> 8;     // tap*27 + oc
    int oc  = r % 27;
    int tap = r / 27;
    float v = (oc < 18) ? ow[(size_t)(oc * CIN + c) * KKT + tap]
                        : mw[(size_t)((oc - 18) * CIN + c) * KKT + tap];
    g_wom[idx] = v;
}

// ---------------- kernel: offset/mod conv + sampling prep ------------------
// grid 256 blocks (b*32 + ytile, 2 rows each), 128 threads (2 rows x 64 cols)
__global__ void k_offmod(const float* __restrict__ off_b, const float* __restrict__ mod_b) {
    __shared__ __align__(16) float sw[27 * CIN];
    int bx = blockIdx.x;
    int b  = bx >> 5;
    int y  = ((bx & 31) << 1) + (threadIdx.x >> 6);
    int xw = threadIdx.x & 63;

    float acc[27];
#pragma unroll
    for (int oc = 0; oc < 18; oc++) acc[oc] = off_b[oc];
#pragma unroll
    for (int oc = 18; oc < 27; oc++) acc[oc] = mod_b[oc - 18];

    const float4* X4 = (const float4*)g_xn;
    for (int tap = 0; tap < 9; tap++) {
        __syncthreads();
        for (int i = threadIdx.x; i < 27 * CIN; i += 128)
            sw[i] = g_wom[tap * 27 * CIN + i];
        __syncthreads();
        int y2 = y + tap / 3 - 1;
        int x2 = xw + tap % 3 - 1;
        if (y2 >= 0 && y2 < HH && x2 >= 0 && x2 < WW) {
            const float4* xp = X4 + (size_t)(b * HWSZ + y2 * WW + x2) * (CIN / 4);
            const float4* wp = (const float4*)sw;
            for (int c4 = 0; c4 < CIN / 4; c4++) {
                float4 xa = xp[c4];
#pragma unroll
                for (int oc = 0; oc < 27; oc++) {
                    float4 wv = wp[oc * (CIN / 4) + c4];
                    acc[oc] += xa.x * wv.x + xa.y * wv.y + xa.z * wv.z + xa.w * wv.w;
                }
            }
        }
    }

    int pos = y * WW + xw;
#pragma unroll
    for (int tap = 0; tap < 9; tap++) {
        float dyo = fminf(fmaxf(acc[2 * tap],     -16.f), 16.f);
        float dxo = fminf(fmaxf(acc[2 * tap + 1], -16.f), 16.f);
        float m   = 1.f / (1.f + __expf(-acc[18 + tap]));
        float py  = dyo + (float)(tap / 3) + (float)y  - 1.f;
        float px  = dxo + (float)(tap % 3) + (float)xw - 1.f;
        float y0f = floorf(py), x0f = floorf(px);
        float ly  = py - y0f,   lx  = px - x0f;
        int y0 = (int)y0f, x0 = (int)x0f;
        bool vy0 = (y0 >= 0)     && (y0 < HH);
        bool vy1 = (y0 + 1 >= 0) && (y0 + 1 < HH);
        bool vx0 = (x0 >= 0)     && (x0 < WW);
        bool vx1 = (x0 + 1 >= 0) && (x0 + 1 < WW);
        float w00 = (1.f - ly) * (1.f - lx) * m * ((vy0 && vx0) ? 1.f : 0.f);
        float w01 = (1.f - ly) * lx         * m * ((vy0 && vx1) ? 1.f : 0.f);
        float w10 = ly * (1.f - lx)         * m * ((vy1 && vx0) ? 1.f : 0.f);
        float w11 = ly * lx                 * m * ((vy1 && vx1) ? 1.f : 0.f);
        int y0c = min(max(y0, 0), HH - 1);
        int y1c = min(max(y0 + 1, 0), HH - 1);
        int x0c = min(max(x0, 0), WW - 1);
        int x1c = min(max(x0 + 1, 0), WW - 1);
        int si = (b * 9 + tap) * HWSZ + pos;
        g_sxy[si] = make_short4((short)y0c, (short)y1c, (short)x0c, (short)x1c);
        g_swt[si] = make_float4(w00, w01, w10, w11);
    }
}

// ---------------- kernel: main deformable implicit GEMM --------------------
// M=128 (spatial), N=128 (oc), K-chunk=16, 256 threads, 8x8 per thread.
// f32x2-packed accumulators along M; B stored value-duplicated in smem.
__global__ void __launch_bounds__(256, 2) k_main(float* __restrict__ out) {
    __shared__ __align__(16) float As[16 * 128];    //  8 KB  [k][m]
    __shared__ __align__(16) float Bsd[16 * 256];   // 16 KB  [k][2n] duplicated

    int mb   = blockIdx.x;           // 0..255
    int b    = mb >> 5;
    int pos0 = (mb & 31) << 7;
    int noff = blockIdx.y << 7;

    int tid  = threadIdx.x;
    int tx   = tid & 15;             // n dir
    int ty   = tid >> 4;             // m dir
    int m    = tid & 127;            // A-fill position
    int ksel = tid >> 7;             // A-fill k half
    int krB  = tid >> 4;             // B-fill row 0..15
    int xcB  = tid & 15;             // B-fill col group

    const float4* X4  = (const float4*)g_xn;
    const float4* WT4 = (const float4*)g_wT;

    unsigned long long acc[4][8];
#pragma unroll
    for (int i = 0; i < 4; i++)
#pragma unroll
        for (int j = 0; j < 8; j++) acc[i][j] = 0ULL;

    for (int tap = 0; tap < 9; tap++) {
        int si = (b * 9 + tap) * HWSZ + pos0 + m;
        short4 s  = g_sxy[si];
        float4 wc = g_swt[si];
        int pb  = b * HWSZ;
        int a00 = (pb + s.x * WW + s.z) << 6;   // float4 base indices
        int a01 = (pb + s.x * WW + s.w) << 6;
        int a10 = (pb + s.y * WW + s.z) << 6;
        int a11 = (pb + s.y * WW + s.w) << 6;

        for (int cc = 0; cc < 16; cc++) {
            int kc = tap * 16 + cc;
            __syncthreads();
            // ---- fill A: this thread covers c = cc*16 + ksel*8 + [0,8)
            int c4 = (cc << 2) + (ksel << 1);
#pragma unroll
            for (int g = 0; g < 2; g++) {
                int c4g = c4 + g;
                float4 v0 = X4[a00 + c4g];
                float4 v1 = X4[a01 + c4g];
                float4 v2 = X4[a10 + c4g];
                float4 v3 = X4[a11 + c4g];
                int kr = (ksel << 3) + (g << 2);
                As[(kr + 0) * 128 + m] = wc.x * v0.x + wc.y * v1.x + wc.z * v2.x + wc.w * v3.x;
                As[(kr + 1) * 128 + m] = wc.x * v0.y + wc.y * v1.y + wc.z * v2.y + wc.w * v3.y;
                As[(kr + 2) * 128 + m] = wc.x * v0.z + wc.y * v1.z + wc.z * v2.z + wc.w * v3.z;
                As[(kr + 3) * 128 + m] = wc.x * v0.w + wc.y * v1.w + wc.z * v2.w + wc.w * v3.w;
            }
            // ---- fill B (duplicated): row krB, cols noff + [0,128)
            {
                const float4* src = WT4 + (size_t)(kc * 16 + krB) * 64 + (noff >> 2);
                float4 s0 = src[xcB];
                float4 s1 = src[xcB + 16];
                float4* dstd = (float4*)(Bsd + krB * 256);
                dstd[xcB * 2]          = make_float4(s0.x, s0.x, s0.y, s0.y);
                dstd[xcB * 2 + 1]      = make_float4(s0.z, s0.z, s0.w, s0.w);
                dstd[32 + xcB * 2]     = make_float4(s1.x, s1.x, s1.y, s1.y);
                dstd[32 + xcB * 2 + 1] = make_float4(s1.z, s1.z, s1.w, s1.w);
            }
            __syncthreads();
            // ---- compute 16 k-steps
            const ulonglong2* A2 = (const ulonglong2*)As;
            const ulonglong2* B2 = (const ulonglong2*)Bsd;
#pragma unroll
            for (int kk = 0; kk < 16; kk++) {
                ulonglong2 ua0 = A2[kk * 32 + ty * 2];
                ulonglong2 ua1 = A2[kk * 32 + ty * 2 + 1];
                unsigned long long ap[4] = {ua0.x, ua0.y, ua1.x, ua1.y};
                ulonglong2 ub0 = B2[kk * 64 + tx * 4 + 0];
                ulonglong2 ub1 = B2[kk * 64 + tx * 4 + 1];
                ulonglong2 ub2 = B2[kk * 64 + tx * 4 + 2];
                ulonglong2 ub3 = B2[kk * 64 + tx * 4 + 3];
                unsigned long long bd[8] = {ub0.x, ub0.y, ub1.x, ub1.y,
                                            ub2.x, ub2.y, ub3.x, ub3.y};
#pragma unroll
                for (int i = 0; i < 4; i++)
#pragma unroll
                    for (int j = 0; j < 8; j++)
                        acc[i][j] = fma2(ap[i], bd[j], acc[i][j]);
            }
        }
    }

    // ---- epilogue: float2 stores (pairs are along M)
    int tm0 = ty << 3;
    int tn0 = tx << 3;
    float* ob = out + ((size_t)(b * COUT + noff + tn0)) * HWSZ + pos0 + tm0;
#pragma unroll
    for (int j = 0; j < 8; j++) {
#pragma unroll
        for (int i2 = 0; i2 < 4; i2++) {
            float2 v = upk2(acc[i2][j]);
            *(float2*)(ob + (size_t)j * HWSZ + i2 * 2) = v;
        }
    }
}

// ---------------- launch ----------------------------------------------------
extern "C" void kernel_launch(void* const* d_in, const int* in_sizes, int n_in,
                              void* d_out, int out_size) {
    const float* x        = (const float*)d_in[0];
    const float* offset_w = (const float*)d_in[1];
    const float* offset_b = (const float*)d_in[2];
    const float* mod_w    = (const float*)d_in[3];
    const float* mod_b    = (const float*)d_in[4];
    const float* reg_w    = (const float*)d_in[5];
    float* out = (float*)d_out;

    k_transpose<<<dim3(128, 8, 8), dim3(32, 8)>>>(x);
    k_wt<<<(KTOT * COUT + 255) / 256, 256>>>(reg_w);
    k_wom<<<(KKT * 27 * CIN + 255) / 256, 256>>>(offset_w, mod_w);
    k_offmod<<<256, 128>>>(offset_b, mod_b);
    k_main<<<dim3(256, 2), 256>>>(out);
}

// round 2
// speedup vs baseline: 2.2895x; 2.2895x over previous
#include <cuda_runtime.h>
#include <cuda_bf16.h>

// Problem constants
#define HH 64
#define WW 64
#define CIN 256
#define COUT 256
#define BB 8
#define KKT 9
#define HWSZ 4096            // H*W
#define KTOT 2304            // 9*256

typedef unsigned long long ull;

// ---------------- scratch (device globals: no allocation allowed) ----------
__device__ float  g_xn[BB * HWSZ * CIN];     // x in NHWC           (33.5 MB)
__device__ float  g_wT[KTOT * COUT];         // W^T [k][oc], k=tap*256+c
__device__ float  g_wom[KKT * 27 * CIN];     // fused off/mod weights [tap][oc][c]
__device__ short4 g_sxy[BB * KKT * HWSZ];    // clamped corner coords (y0,y1,x0,x1)
__device__ float4 g_swt[BB * KKT * HWSZ];    // bilinear*mask*valid weights

// ---------------- f32x2 helpers --------------------------------------------
__device__ __forceinline__ ull fma2(ull a, ull b, ull c) {
    ull d;
    asm("fma.rn.f32x2 %0, %1, %2, %3;" : "=l"(d) : "l"(a), "l"(b), "l"(c));
    return d;
}
__device__ __forceinline__ float2 upk2(ull v) {
    float2 r;
    asm("mov.b64 {%0, %1}, %2;" : "=f"(r.x), "=f"(r.y) : "l"(v));
    return r;
}
__device__ __forceinline__ ull dup2(float v) {
    ull r;
    asm("mov.b64 %0, {%1, %1};" : "=l"(r) : "f"(v));
    return r;
}
__device__ __forceinline__ float sum2(ull v) {
    float2 r = upk2(v);
    return r.x + r.y;
}

// ---------------- kernel: NCHW -> NHWC transpose of x ----------------------
__global__ void k_transpose(const float* __restrict__ x) {
    __shared__ float tile[32][33];
    int b  = blockIdx.z;
    int p0 = blockIdx.x * 32;   // spatial
    int c0 = blockIdx.y * 32;   // channel
    const float* xb = x   + (size_t)b * (CIN * HWSZ);
    float*       ob = g_xn + (size_t)b * (HWSZ * CIN);
    int tx = threadIdx.x, ty = threadIdx.y;
#pragma unroll
    for (int i = 0; i < 4; i++)
        tile[ty + i * 8][tx] = xb[(size_t)(c0 + ty + i * 8) * HWSZ + p0 + tx];
    __syncthreads();
#pragma unroll
    for (int i = 0; i < 4; i++)
        ob[(size_t)(p0 + ty + i * 8) * CIN + c0 + tx] = tile[tx][ty + i * 8];
}

// ---------------- kernel: transpose reg_w to [k][oc] -----------------------
__global__ void k_wt(const float* __restrict__ reg_w) {
    int idx = blockIdx.x * 256 + threadIdx.x;   // = k*256 + oc
    if (idx >= KTOT * COUT) return;
    int oc  = idx & 255;
    int k   = idx >> 8;
    int tap = k >> 8;
    int c   = k & 255;
    g_wT[idx] = reg_w[(size_t)(oc * CIN + c) * KKT + tap];
}

// ---------------- kernel: fuse offset_w + mod_w into [tap][oc][c] ----------
__global__ void k_wom(const float* __restrict__ ow, const float* __restrict__ mw) {
    int idx = blockIdx.x * 256 + threadIdx.x;
    if (idx >= KKT * 27 * CIN) return;
    int c   = idx & 255;
    int r   = idx >> 8;     // tap*27 + oc
    int oc  = r % 27;
    int tap = r / 27;
    float v = (oc < 18) ? ow[(size_t)(oc * CIN + c) * KKT + tap]
                        : mw[(size_t)((oc - 18) * CIN + c) * KKT + tap];
    g_wom[idx] = v;
}

// ---------------- kernel: offset/mod conv + sampling prep ------------------
// 512 blocks = (b, y-row). 256 threads = 64 cols x 4 channel groups.
// Each thread accumulates 27 outputs over its 64-channel slice (f32x2 packed),
// then cross-group smem reduction; cg0 does the nonlinearity + sampling prep.
__global__ void __launch_bounds__(256) k_offmod(const float* __restrict__ off_b,
                                                const float* __restrict__ mod_b) {
    __shared__ __align__(16) float sw[27 * CIN];        // 27648 B
    __shared__ float red[3][64][28];                    // 21504 B  (48K total)
    int blk = blockIdx.x;
    int b   = blk >> 6;
    int y   = blk & 63;
    int tid = threadIdx.x;
    int p   = tid & 63;        // x col
    int cg  = tid >> 6;        // channel group 0..3

    ull acc[27];
#pragma unroll
    for (int oc = 0; oc < 27; oc++) acc[oc] = 0ULL;

    const float4* X4 = (const float4*)g_xn;

    for (int tap = 0; tap < 9; tap++) {
        __syncthreads();
        {
            const float4* wsrc = (const float4*)(g_wom + tap * 27 * CIN);
            float4* wdst = (float4*)sw;
            for (int i = tid; i < 27 * 64; i += 256) wdst[i] = wsrc[i];
        }
        __syncthreads();
        int y2 = y + tap / 3 - 1;
        int x2 = p + tap % 3 - 1;
        if (y2 >= 0 && y2 < HH && x2 >= 0 && x2 < WW) {
            const float4* xp = X4 + (size_t)(b * HWSZ + y2 * WW + x2) * 64 + cg * 16;
#pragma unroll 4
            for (int c4 = 0; c4 < 16; c4++) {
                float4 xa = xp[c4];
                ulonglong2 ux = *(ulonglong2*)&xa;
#pragma unroll
                for (int oc = 0; oc < 27; oc++) {
                    ulonglong2 uw = *(const ulonglong2*)&sw[oc * CIN + cg * 64 + c4 * 4];
                    acc[oc] = fma2(ux.x, uw.x, acc[oc]);
                    acc[oc] = fma2(ux.y, uw.y, acc[oc]);
                }
            }
        }
    }

    __syncthreads();
    if (cg > 0) {
#pragma unroll
        for (int oc = 0; oc < 27; oc++) red[cg - 1][p][oc] = sum2(acc[oc]);
    }
    __syncthreads();
    if (cg == 0) {
        float a[27];
#pragma unroll
        for (int oc = 0; oc < 27; oc++) {
            float bias = (oc < 18) ? off_b[oc] : mod_b[oc - 18];
            a[oc] = sum2(acc[oc]) + red[0][p][oc] + red[1][p][oc] + red[2][p][oc] + bias;
        }
        int pos = y * WW + p;
#pragma unroll
        for (int tap = 0; tap < 9; tap++) {
            float dyo = fminf(fmaxf(a[2 * tap],     -16.f), 16.f);
            float dxo = fminf(fmaxf(a[2 * tap + 1], -16.f), 16.f);
            float m   = 1.f / (1.f + __expf(-a[18 + tap]));
            float py  = dyo + (float)(tap / 3) + (float)y - 1.f;
            float px  = dxo + (float)(tap % 3) + (float)p - 1.f;
            float y0f = floorf(py), x0f = floorf(px);
            float ly  = py - y0f,   lx  = px - x0f;
            int y0 = (int)y0f, x0 = (int)x0f;
            bool vy0 = (y0 >= 0)     && (y0 < HH);
            bool vy1 = (y0 + 1 >= 0) && (y0 + 1 < HH);
            bool vx0 = (x0 >= 0)     && (x0 < WW);
            bool vx1 = (x0 + 1 >= 0) && (x0 + 1 < WW);
            float w00 = (1.f - ly) * (1.f - lx) * m * ((vy0 && vx0) ? 1.f : 0.f);
            float w01 = (1.f - ly) * lx         * m * ((vy0 && vx1) ? 1.f : 0.f);
            float w10 = ly * (1.f - lx)         * m * ((vy1 && vx0) ? 1.f : 0.f);
            float w11 = ly * lx                 * m * ((vy1 && vx1) ? 1.f : 0.f);
            int y0c = min(max(y0, 0), HH - 1);
            int y1c = min(max(y0 + 1, 0), HH - 1);
            int x0c = min(max(x0, 0), WW - 1);
            int x1c = min(max(x0 + 1, 0), WW - 1);
            int si = (b * 9 + tap) * HWSZ + pos;
            g_sxy[si] = make_short4((short)y0c, (short)y1c, (short)x0c, (short)x1c);
            g_swt[si] = make_float4(w00, w01, w10, w11);
        }
    }
}

// ---------------- kernel: main deformable implicit GEMM --------------------
// 128x128 block tile, K staged 16/stage, 256 threads, 8x8 per thread.
// Accumulators f32x2-packed along M. B in smem NON-duplicated (conflict-free
// float4 reads); (b,b) pairs built in registers via mov.b64 (ALU pipe).
__global__ void __launch_bounds__(256, 2) k_main(float* __restrict__ out) {
    __shared__ __align__(16) float As[16 * 128];    // 8 KB [k][m]
    __shared__ __align__(16) float Bs[16 * 128];    // 8 KB [k][n]

    int mb   = blockIdx.x;           // 0..255
    int b    = mb >> 5;
    int pos0 = (mb & 31) << 7;
    int noff = blockIdx.y << 7;

    int tid  = threadIdx.x;
    int tx   = tid & 15;             // n dir
    int ty   = tid >> 4;             // m granule (8 rows)
    int m    = tid & 127;            // A-fill position
    int ksel = tid >> 7;             // A-fill k half
    int rB   = tid >> 4;             // B-fill row 0..15
    int cB   = tid & 15;             // B-fill col group

    const float4* X4  = (const float4*)g_xn;
    const float4* WT4 = (const float4*)g_wT;

    ull acc[4][8];
#pragma unroll
    for (int i = 0; i < 4; i++)
#pragma unroll
        for (int j = 0; j < 8; j++) acc[i][j] = 0ULL;

    for (int tap = 0; tap < 9; tap++) {
        int si = (b * 9 + tap) * HWSZ + pos0 + m;
        short4 s  = g_sxy[si];
        float4 wc = g_swt[si];
        int pb  = b * HWSZ;
        int a00 = (pb + s.x * WW + s.z) << 6;   // float4 base indices
        int a01 = (pb + s.x * WW + s.w) << 6;
        int a10 = (pb + s.y * WW + s.z) << 6;
        int a11 = (pb + s.y * WW + s.w) << 6;

        for (int cc = 0; cc < 16; cc++) {
            __syncthreads();
            // ---- B fill (non-duplicated [k][n]); conflict-free STS.128
            {
                int kg = tap * 256 + cc * 16 + rB;
                const float4* src = WT4 + (size_t)kg * 64 + (noff >> 2);
                float4 s0 = src[cB];
                float4 s1 = src[cB + 16];
                *(float4*)&Bs[rB * 128 + cB * 4]      = s0;
                *(float4*)&Bs[rB * 128 + 64 + cB * 4] = s1;
            }
            // ---- A fill: c = cc*16 + ksel*8 + [0,8)
            int c4 = (cc << 2) + (ksel << 1);
#pragma unroll
            for (int g = 0; g < 2; g++) {
                int c4g = c4 + g;
                float4 v0 = X4[a00 + c4g];
                float4 v1 = X4[a01 + c4g];
                float4 v2 = X4[a10 + c4g];
                float4 v3 = X4[a11 + c4g];
                int kr = (ksel << 3) + (g << 2);
                As[(kr + 0) * 128 + m] = wc.x * v0.x + wc.y * v1.x + wc.z * v2.x + wc.w * v3.x;
                As[(kr + 1) * 128 + m] = wc.x * v0.y + wc.y * v1.y + wc.z * v2.y + wc.w * v3.y;
                As[(kr + 2) * 128 + m] = wc.x * v0.z + wc.y * v1.z + wc.z * v2.z + wc.w * v3.z;
                As[(kr + 3) * 128 + m] = wc.x * v0.w + wc.y * v1.w + wc.z * v2.w + wc.w * v3.w;
            }
            __syncthreads();
            // ---- compute 16 k-steps
#pragma unroll
            for (int kk = 0; kk < 16; kk++) {
                const ulonglong2* A2 = (const ulonglong2*)(As + kk * 128 + ty * 8);
                ulonglong2 ua0 = A2[0];           // m pairs (0,1),(2,3)
                ulonglong2 ua1 = A2[1];           // m pairs (4,5),(6,7)
                ull ap[4] = {ua0.x, ua0.y, ua1.x, ua1.y};
                float4 b0 = *(const float4*)(Bs + kk * 128 + tx * 4);        // n = 4tx..4tx+3
                float4 b1 = *(const float4*)(Bs + kk * 128 + 64 + tx * 4);   // n = 64+4tx..
                ull bd[8] = {dup2(b0.x), dup2(b0.y), dup2(b0.z), dup2(b0.w),
                             dup2(b1.x), dup2(b1.y), dup2(b1.z), dup2(b1.w)};
#pragma unroll
                for (int i = 0; i < 4; i++)
#pragma unroll
                    for (int j = 0; j < 8; j++)
                        acc[i][j] = fma2(ap[i], bd[j], acc[i][j]);
            }
        }
    }

    // ---- epilogue: float2 stores (pairs along M)
    int mbase = pos0 + (ty << 3);
#pragma unroll
    for (int j = 0; j < 8; j++) {
        int oc = noff + ((j < 4) ? (4 * tx + j) : (64 + 4 * tx + (j - 4)));
        float* ob = out + (size_t)(b * COUT + oc) * HWSZ + mbase;
#pragma unroll
        for (int i2 = 0; i2 < 4; i2++) {
            float2 v = upk2(acc[i2][j]);
            *(float2*)(ob + i2 * 2) = v;
        }
    }
}

// ---------------- launch ----------------------------------------------------
extern "C" void kernel_launch(void* const* d_in, const int* in_sizes, int n_in,
                              void* d_out, int out_size) {
    const float* x        = (const float*)d_in[0];
    const float* offset_w = (const float*)d_in[1];
    const float* offset_b = (const float*)d_in[2];
    const float* mod_w    = (const float*)d_in[3];
    const float* mod_b    = (const float*)d_in[4];
    const float* reg_w    = (const float*)d_in[5];
    float* out = (float*)d_out;

    k_transpose<<<dim3(128, 8, 8), dim3(32, 8)>>>(x);
    k_wt<<<(KTOT * COUT + 255) / 256, 256>>>(reg_w);
    k_wom<<<(KKT * 27 * CIN + 255) / 256, 256>>>(offset_w, mod_w);
    k_offmod<<<512, 256>>>(offset_b, mod_b);
    k_main<<<dim3(256, 2), 256>>>(out);
}

// round 4
// speedup vs baseline: 3.1799x; 1.3889x over previous
#include <cuda_runtime.h>
#include <cuda_bf16.h>

// Problem constants
#define HH 64
#define WW 64
#define CIN 256
#define COUT 256
#define BB 8
#define KKT 9
#define HWSZ 4096            // H*W
#define KTOT 2304            // 9*256

typedef unsigned long long ull;

// ---------------- scratch (device globals: no allocation allowed) ----------
__device__ float  g_xn[BB * HWSZ * CIN];     // x in NHWC (33.5 MB)
__device__ float  g_wT[KTOT * COUT];         // W^T [k][oc], k=tap*256+c
__device__ float  g_wom[KKT * 27 * CIN];     // fused off/mod weights [tap][oc][c]
__device__ short4 g_sxy[BB * KKT * HWSZ];    // clamped corner coords
__device__ float4 g_swt[BB * KKT * HWSZ];    // bilinear*mask*valid weights
// im2col A, tiled: [(bt*32+mchunk)*16+cc][16 k][128 m]  (302 MB)
__device__ float  g_A[(size_t)BB * KKT * CIN * HWSZ];

// ---------------- helpers ---------------------------------------------------
__device__ __forceinline__ ull fma2(ull a, ull b, ull c) {
    ull d;
    asm("fma.rn.f32x2 %0, %1, %2, %3;" : "=l"(d) : "l"(a), "l"(b), "l"(c));
    return d;
}
__device__ __forceinline__ float2 upk2(ull v) {
    float2 r;
    asm("mov.b64 {%0, %1}, %2;" : "=f"(r.x), "=f"(r.y) : "l"(v));
    return r;
}
__device__ __forceinline__ ull dup2(float v) {
    ull r;
    asm("mov.b64 %0, {%1, %1};" : "=l"(r) : "f"(v));
    return r;
}
__device__ __forceinline__ float sum2(ull v) {
    float2 r = upk2(v);
    return r.x + r.y;
}
__device__ __forceinline__ void cpa16(unsigned int s, const void* g) {
    asm volatile("cp.async.cg.shared.global [%0], [%1], 16;" :: "r"(s), "l"(g));
}

// ---------------- kernel: NCHW -> NHWC transpose of x ----------------------
__global__ void k_transpose(const float* __restrict__ x) {
    __shared__ float tile[32][33];
    int b  = blockIdx.z;
    int p0 = blockIdx.x * 32;
    int c0 = blockIdx.y * 32;
    const float* xb = x    + (size_t)b * (CIN * HWSZ);
    float*       ob = g_xn + (size_t)b * (HWSZ * CIN);
    int tx = threadIdx.x, ty = threadIdx.y;
#pragma unroll
    for (int i = 0; i < 4; i++)
        tile[ty + i * 8][tx] = xb[(size_t)(c0 + ty + i * 8) * HWSZ + p0 + tx];
    __syncthreads();
#pragma unroll
    for (int i = 0; i < 4; i++)
        ob[(size_t)(p0 + ty + i * 8) * CIN + c0 + tx] = tile[tx][ty + i * 8];
}

// ---------------- kernel: transpose reg_w to [k][oc] -----------------------
__global__ void k_wt(const float* __restrict__ reg_w) {
    int idx = blockIdx.x * 256 + threadIdx.x;
    if (idx >= KTOT * COUT) return;
    int oc  = idx & 255;
    int k   = idx >> 8;
    int tap = k >> 8;
    int c   = k & 255;
    g_wT[idx] = reg_w[(size_t)(oc * CIN + c) * KKT + tap];
}

// ---------------- kernel: fuse offset_w + mod_w into [tap][oc][c] ----------
__global__ void k_wom(const float* __restrict__ ow, const float* __restrict__ mw) {
    int idx = blockIdx.x * 256 + threadIdx.x;
    if (idx >= KKT * 27 * CIN) return;
    int c   = idx & 255;
    int r   = idx >> 8;
    int oc  = r % 27;
    int tap = r / 27;
    float v = (oc < 18) ? ow[(size_t)(oc * CIN + c) * KKT + tap]
                        : mw[(size_t)((oc - 18) * CIN + c) * KKT + tap];
    g_wom[idx] = v;
}

// ---------------- kernel: offset/mod conv + sampling prep ------------------
__global__ void __launch_bounds__(256) k_offmod(const float* __restrict__ off_b,
                                                const float* __restrict__ mod_b) {
    __shared__ __align__(16) float sw[27 * CIN];
    __shared__ float red[3][64][28];
    int blk = blockIdx.x;
    int b   = blk >> 6;
    int y   = blk & 63;
    int tid = threadIdx.x;
    int p   = tid & 63;
    int cg  = tid >> 6;

    ull acc[27];
#pragma unroll
    for (int oc = 0; oc < 27; oc++) acc[oc] = 0ULL;

    const float4* X4 = (const float4*)g_xn;

    for (int tap = 0; tap < 9; tap++) {
        __syncthreads();
        {
            const float4* wsrc = (const float4*)(g_wom + tap * 27 * CIN);
            float4* wdst = (float4*)sw;
            for (int i = tid; i < 27 * 64; i += 256) wdst[i] = wsrc[i];
        }
        __syncthreads();
        int y2 = y + tap / 3 - 1;
        int x2 = p + tap % 3 - 1;
        if (y2 >= 0 && y2 < HH && x2 >= 0 && x2 < WW) {
            const float4* xp = X4 + (size_t)(b * HWSZ + y2 * WW + x2) * 64 + cg * 16;
#pragma unroll 4
            for (int c4 = 0; c4 < 16; c4++) {
                float4 xa = xp[c4];
                ulonglong2 ux = *(ulonglong2*)&xa;
#pragma unroll
                for (int oc = 0; oc < 27; oc++) {
                    ulonglong2 uw = *(const ulonglong2*)&sw[oc * CIN + cg * 64 + c4 * 4];
                    acc[oc] = fma2(ux.x, uw.x, acc[oc]);
                    acc[oc] = fma2(ux.y, uw.y, acc[oc]);
                }
            }
        }
    }

    __syncthreads();
    if (cg > 0) {
#pragma unroll
        for (int oc = 0; oc < 27; oc++) red[cg - 1][p][oc] = sum2(acc[oc]);
    }
    __syncthreads();
    if (cg == 0) {
        float a[27];
#pragma unroll
        for (int oc = 0; oc < 27; oc++) {
            float bias = (oc < 18) ? off_b[oc] : mod_b[oc - 18];
            a[oc] = sum2(acc[oc]) + red[0][p][oc] + red[1][p][oc] + red[2][p][oc] + bias;
        }
        int pos = y * WW + p;
#pragma unroll
        for (int tap = 0; tap < 9; tap++) {
            float dyo = fminf(fmaxf(a[2 * tap],     -16.f), 16.f);
            float dxo = fminf(fmaxf(a[2 * tap + 1], -16.f), 16.f);
            float m   = 1.f / (1.f + __expf(-a[18 + tap]));
            float py  = dyo + (float)(tap / 3) + (float)y - 1.f;
            float px  = dxo + (float)(tap % 3) + (float)p - 1.f;
            float y0f = floorf(py), x0f = floorf(px);
            float ly  = py - y0f,   lx  = px - x0f;
            int y0 = (int)y0f, x0 = (int)x0f;
            bool vy0 = (y0 >= 0)     && (y0 < HH);
            bool vy1 = (y0 + 1 >= 0) && (y0 + 1 < HH);
            bool vx0 = (x0 >= 0)     && (x0 < WW);
            bool vx1 = (x0 + 1 >= 0) && (x0 + 1 < WW);
            float w00 = (1.f - ly) * (1.f - lx) * m * ((vy0 && vx0) ? 1.f : 0.f);
            float w01 = (1.f - ly) * lx         * m * ((vy0 && vx1) ? 1.f : 0.f);
            float w10 = ly * (1.f - lx)         * m * ((vy1 && vx0) ? 1.f : 0.f);
            float w11 = ly * lx                 * m * ((vy1 && vx1) ? 1.f : 0.f);
            int y0c = min(max(y0, 0), HH - 1);
            int y1c = min(max(y0 + 1, 0), HH - 1);
            int x0c = min(max(x0, 0), WW - 1);
            int x1c = min(max(x0 + 1, 0), WW - 1);
            int si = (b * 9 + tap) * HWSZ + pos;
            g_sxy[si] = make_short4((short)y0c, (short)y1c, (short)x0c, (short)x1c);
            g_swt[si] = make_float4(w00, w01, w10, w11);
        }
    }
}

// ---------------- kernel: bilinear gather -> tiled im2col g_A --------------
// blocks: 72 (b,tap) * 128 chunks of 32 px. 256 thr: px=tid>>3, cs=tid&7.
// Channel-major lanes: 8 lanes read 128B contiguous channel run per pixel.
__global__ void __launch_bounds__(256) k_gather() {
    __shared__ float sA[256 * 33];          // [c][px] pad 33: conflict-free both phases
    int blk = blockIdx.x;
    int bt  = blk >> 7;                     // b*9+tap
    int p32 = blk & 127;
    int b   = bt / 9;
    int pos0 = p32 << 5;
    int tid = threadIdx.x;
    int px  = tid >> 3;
    int cs  = tid & 7;

    int si = bt * HWSZ + pos0 + px;
    short4 s  = g_sxy[si];
    float4 wc = g_swt[si];
    int pb  = b * HWSZ;
    int a00 = (pb + s.x * WW + s.z) << 6;
    int a01 = (pb + s.x * WW + s.w) << 6;
    int a10 = (pb + s.y * WW + s.z) << 6;
    int a11 = (pb + s.y * WW + s.w) << 6;
    const float4* X4 = (const float4*)g_xn;

#pragma unroll
    for (int i = 0; i < 8; i++) {
        int c4 = i * 8 + cs;
        float4 v0 = X4[a00 + c4];
        float4 v1 = X4[a01 + c4];
        float4 v2 = X4[a10 + c4];
        float4 v3 = X4[a11 + c4];
        int c = c4 * 4;
        sA[(c + 0) * 33 + px] = wc.x * v0.x + wc.y * v1.x + wc.z * v2.x + wc.w * v3.x;
        sA[(c + 1) * 33 + px] = wc.x * v0.y + wc.y * v1.y + wc.z * v2.y + wc.w * v3.y;
        sA[(c + 2) * 33 + px] = wc.x * v0.z + wc.y * v1.z + wc.z * v2.z + wc.w * v3.z;
        sA[(c + 3) * 33 + px] = wc.x * v0.w + wc.y * v1.w + wc.z * v2.w + wc.w * v3.w;
    }
    __syncthreads();

    // write tiled: g_A[((bt*32+mch)*16+cc)*2048 + kr*128 + m]
    size_t obase = ((size_t)bt * 32 + (p32 >> 2)) * 16 * 2048;
    int mo  = (p32 & 3) << 5;
    int r8  = tid >> 5;                     // 8 c-rows per pass
    int pxw = tid & 31;
#pragma unroll 8
    for (int pass = 0; pass < 32; pass++) {
        int c = pass * 8 + r8;
        g_A[obase + (size_t)(c >> 4) * 2048 + (c & 15) * 128 + mo + pxw] = sA[c * 33 + pxw];
    }
}

// ---------------- kernel: main GEMM (cp.async double-buffered) -------------
// 128x128 tile, 144 stages of K=16, 256 threads, 8x8 per thread, f32x2 accs.
__global__ void __launch_bounds__(256, 2) k_main(float* __restrict__ out) {
    __shared__ __align__(16) float As[2][16 * 128];   // 16 KB
    __shared__ __align__(16) float Bs[2][16 * 128];   // 16 KB

    int mb   = blockIdx.x;           // b*32 + mchunk
    int b    = mb >> 5;
    int mch  = mb & 31;
    int pos0 = mch << 7;
    int noff = blockIdx.y << 7;

    int tid = threadIdx.x;
    int tx  = tid & 15;
    int ty  = tid >> 4;

    unsigned int sa0 = (unsigned int)__cvta_generic_to_shared(&As[0][0]);
    unsigned int sa1 = (unsigned int)__cvta_generic_to_shared(&As[1][0]);
    unsigned int sb0 = (unsigned int)__cvta_generic_to_shared(&Bs[0][0]);
    unsigned int sb1 = (unsigned int)__cvta_generic_to_shared(&Bs[1][0]);

    // per-block A base (float index): stage s adds (s>>4)*1048576 + (s&15)*2048
    size_t abase = ((size_t)b * 9 * 32 + mch) * 16 * 2048;
    const float* Ag = g_A + abase + tid * 4;          // + second chunk at +1024 floats
    int krB = tid >> 4, cB = tid & 15;

    ull acc[4][8];
#pragma unroll
    for (int i = 0; i < 4; i++)
#pragma unroll
        for (int j = 0; j < 8; j++) acc[i][j] = 0ULL;

#define ISSUE(s, sa, sb)                                                          \
    {                                                                             \
        const float* ap = Ag + (size_t)((s) >> 4) * 1048576 + ((s) & 15) * 2048;  \
        cpa16((sa) + tid * 16, ap);                                               \
        cpa16((sa) + 4096 + tid * 16, ap + 1024);                                 \
        const float* bp = g_wT + (size_t)((s) * 16 + krB) * 256 + noff + cB * 4;  \
        cpa16((sb) + krB * 512 + cB * 16, bp);                                    \
        cpa16((sb) + krB * 512 + 256 + cB * 16, bp + 64);                         \
    }

    ISSUE(0, sa0, sb0);
    asm volatile("cp.async.commit_group;" ::: "memory");

    for (int s = 0; s < 144; s++) {
        if (s < 143) {
            if ((s + 1) & 1) { ISSUE(s + 1, sa1, sb1); }
            else             { ISSUE(s + 1, sa0, sb0); }
        }
        asm volatile("cp.async.commit_group;" ::: "memory");
        asm volatile("cp.async.wait_group 1;" ::: "memory");
        __syncthreads();

        const float* Ab = (s & 1) ? &As[1][0] : &As[0][0];
        const float* Bb = (s & 1) ? &Bs[1][0] : &Bs[0][0];
#pragma unroll
        for (int kk = 0; kk < 16; kk++) {
            const ulonglong2* A2 = (const ulonglong2*)(Ab + kk * 128 + ty * 8);
            ulonglong2 ua0 = A2[0];
            ulonglong2 ua1 = A2[1];
            ull ap[4] = {ua0.x, ua0.y, ua1.x, ua1.y};
            float4 b0 = *(const float4*)(Bb + kk * 128 + tx * 4);
            float4 b1 = *(const float4*)(Bb + kk * 128 + 64 + tx * 4);
            ull bd[8] = {dup2(b0.x), dup2(b0.y), dup2(b0.z), dup2(b0.w),
                         dup2(b1.x), dup2(b1.y), dup2(b1.z), dup2(b1.w)};
#pragma unroll
            for (int i = 0; i < 4; i++)
#pragma unroll
                for (int j = 0; j < 8; j++)
                    acc[i][j] = fma2(ap[i], bd[j], acc[i][j]);
        }
        __syncthreads();
    }
#undef ISSUE

    // ---- epilogue: float2 stores (pairs along M)
    int mbase = pos0 + (ty << 3);
#pragma unroll
    for (int j = 0; j < 8; j++) {
        int oc = noff + ((j < 4) ? (4 * tx + j) : (64 + 4 * tx + (j - 4)));
        float* ob = out + (size_t)(b * COUT + oc) * HWSZ + mbase;
#pragma unroll
        for (int i2 = 0; i2 < 4; i2++) {
            float2 v = upk2(acc[i2][j]);
            *(float2*)(ob + i2 * 2) = v;
        }
    }
}

// ---------------- launch ----------------------------------------------------
extern "C" void kernel_launch(void* const* d_in, const int* in_sizes, int n_in,
                              void* d_out, int out_size) {
    const float* x        = (const float*)d_in[0];
    const float* offset_w = (const float*)d_in[1];
    const float* offset_b = (const float*)d_in[2];
    const float* mod_w    = (const float*)d_in[3];
    const float* mod_b    = (const float*)d_in[4];
    const float* reg_w    = (const float*)d_in[5];
    float* out = (float*)d_out;

    k_transpose<<<dim3(128, 8, 8), dim3(32, 8)>>>(x);
    k_wt<<<(KTOT * COUT + 255) / 256, 256>>>(reg_w);
    k_wom<<<(KKT * 27 * CIN + 255) / 256, 256>>>(offset_w, mod_w);
    k_offmod<<<512, 256>>>(offset_b, mod_b);
    k_gather<<<72 * 128, 256>>>();
    k_main<<<dim3(256, 2), 256>>>(out);
}